// round 5
// baseline (speedup 1.0000x reference)
#include <cuda_runtime.h>
#include <cuda_bf16.h>
#include <math.h>

#define NN 50000
#define EE 800000
#define HH 128
#define DOUT 64

// ---------------- device scratch (no allocations allowed) ----------------
__device__ float g_h[(size_t)NN * HH];
__device__ float g_xw[(size_t)NN * HH];
__device__ float g_P[(size_t)NN * HH];
__device__ float g_Q[(size_t)NN * HH];
__device__ float g_as[NN];
__device__ float g_ad[NN];
__device__ int   g_cnt[NN];          // histogram, then reused as scatter cursor
__device__ int   g_off[NN + 1];      // CSR offsets (by dst)
__device__ int   g_csr[EE + NN];     // src ids per dst bucket (incl. self loops)

// ---------------- CSR build ----------------
__global__ void init_cnt(int* cnt, int n) {
    int i = blockIdx.x * blockDim.x + threadIdx.x;
    if (i < n) cnt[i] = 1;  // self loop
}

__global__ void count_dst(const int* __restrict__ dst, int* cnt, int e) {
    int i = blockIdx.x * blockDim.x + threadIdx.x;
    if (i < e) atomicAdd(&cnt[dst[i]], 1);
}

// single-block exclusive scan; also initializes cursor (reuses cnt array)
__global__ void scan_kernel(int* cnt, int* off, int n) {
    __shared__ int sh[1024];
    __shared__ int carry;
    if (threadIdx.x == 0) carry = 0;
    __syncthreads();
    for (int base = 0; base < n; base += 1024) {
        int i = base + threadIdx.x;
        int v = (i < n) ? cnt[i] : 0;
        sh[threadIdx.x] = v;
        __syncthreads();
        for (int d = 1; d < 1024; d <<= 1) {
            int t = (threadIdx.x >= d) ? sh[threadIdx.x - d] : 0;
            __syncthreads();
            sh[threadIdx.x] += t;
            __syncthreads();
        }
        int incl = sh[threadIdx.x];
        int excl = incl - v + carry;
        if (i < n) { off[i] = excl; cnt[i] = excl; }  // cnt becomes cursor
        __syncthreads();
        if (threadIdx.x == 1023) carry += sh[1023];
        __syncthreads();
    }
    if (threadIdx.x == 0) off[n] = carry;
}

__global__ void csr_fill(const int* __restrict__ src, const int* __restrict__ dst,
                         int* cursor, int* csr, int e, int n) {
    int i = blockIdx.x * blockDim.x + threadIdx.x;
    int total = e + n;
    if (i >= total) return;
    int s, d;
    if (i < e) { s = src[i]; d = dst[i]; }
    else       { s = d = i - e; }
    int pos = atomicAdd(&cursor[d], 1);
    csr[pos] = s;
}

// ---------------- GEMM: C[M x Nc] = act(A[M x 128] @ B[128 x Nc] + bias) ----------------
// BM=BN=64, BK=16, 256 threads, 4x4 micro-tiles.
template<bool RELU>
__global__ void gemm128(const float* __restrict__ A, const float* __restrict__ B,
                        const float* __restrict__ bias, float* __restrict__ C,
                        int M, int Nc) {
    const int BM = 64, BN = 64, BK = 16;
    __shared__ float As[BK][BM + 1];
    __shared__ float Bs[BK][BN];
    int tx = threadIdx.x % 16, ty = threadIdx.x / 16;
    int row0 = blockIdx.y * BM;
    int col0 = blockIdx.x * BN;
    float acc[4][4] = {};
    for (int kt = 0; kt < 128; kt += BK) {
        for (int i = threadIdx.x; i < BM * BK; i += 256) {
            int r = i / BK, c = i % BK;
            int gr = row0 + r;
            As[c][r] = (gr < M) ? A[(size_t)gr * 128 + kt + c] : 0.f;
        }
        for (int i = threadIdx.x; i < BK * BN; i += 256) {
            int r = i / BN, c = i % BN;
            Bs[r][c] = B[(size_t)(kt + r) * Nc + col0 + c];
        }
        __syncthreads();
#pragma unroll
        for (int k = 0; k < BK; k++) {
            float a[4], b[4];
#pragma unroll
            for (int i = 0; i < 4; i++) a[i] = As[k][ty * 4 + i];
#pragma unroll
            for (int j = 0; j < 4; j++) b[j] = Bs[k][tx * 4 + j];
#pragma unroll
            for (int i = 0; i < 4; i++)
#pragma unroll
                for (int j = 0; j < 4; j++) acc[i][j] += a[i] * b[j];
        }
        __syncthreads();
    }
#pragma unroll
    for (int i = 0; i < 4; i++) {
        int gr = row0 + ty * 4 + i;
        if (gr >= M) continue;
#pragma unroll
        for (int j = 0; j < 4; j++) {
            int gc = col0 + tx * 4 + j;
            float v = acc[i][j];
            if (bias) v += bias[gc];
            if (RELU) v = fmaxf(v, 0.f);
            C[(size_t)gr * Nc + gc] = v;
        }
    }
}

// ---------------- alpha_s / alpha_d: per-node dot products ----------------
__global__ void compute_alpha(const float* __restrict__ xw,
                              const float* __restrict__ a_s, const float* __restrict__ a_d,
                              float* __restrict__ out_s, float* __restrict__ out_d, int n) {
    int w = (blockIdx.x * blockDim.x + threadIdx.x) >> 5;
    int lane = threadIdx.x & 31;
    if (w >= n) return;
    const float* row = xw + (size_t)w * HH;
    float ss = 0.f, sd = 0.f;
#pragma unroll
    for (int i = 0; i < 4; i++) {
        int c = lane + 32 * i;
        float v = row[c];
        ss += v * a_s[c];
        sd += v * a_d[c];
    }
#pragma unroll
    for (int o = 16; o; o >>= 1) {
        ss += __shfl_xor_sync(~0u, ss, o);
        sd += __shfl_xor_sync(~0u, sd, o);
    }
    if (lane == 0) { out_s[w] = ss; out_d[w] = sd; }
}

// ---------------- GAT softmax + aggregation (warp per dst node, in-place h) --------------
__global__ void gat_aggregate(const float* __restrict__ xw,
                              const int* __restrict__ off, const int* __restrict__ csr,
                              const float* __restrict__ as_, const float* __restrict__ ad_,
                              const float* __restrict__ bias,
                              float* __restrict__ h, int n) {
    int v = (blockIdx.x * blockDim.x + threadIdx.x) >> 5;
    int lane = threadIdx.x & 31;
    if (v >= n) return;
    int o0 = off[v], o1 = off[v + 1];
    float ad = ad_[v];

    // pass 1: max logit (lanes parallel over edges)
    float m = -INFINITY;
    for (int e = o0 + lane; e < o1; e += 32) {
        int u = csr[e];
        float t = as_[u] + ad;
        t = (t > 0.f) ? t : 0.2f * t;
        m = fmaxf(m, t);
    }
#pragma unroll
    for (int o = 16; o; o >>= 1) m = fmaxf(m, __shfl_xor_sync(~0u, m, o));

    // pass 2: exp-weighted accumulate (warp marches edges together, 4 cols per lane)
    float s = 0.f;
    float a0 = 0.f, a1 = 0.f, a2 = 0.f, a3 = 0.f;
    for (int e = o0; e < o1; e++) {
        int u = csr[e];
        float t = as_[u] + ad;
        t = (t > 0.f) ? t : 0.2f * t;
        float p = __expf(t - m);
        s += p;
        const float* row = xw + (size_t)u * HH;
        a0 += p * row[lane];
        a1 += p * row[lane + 32];
        a2 += p * row[lane + 64];
        a3 += p * row[lane + 96];
    }
    float inv = 1.f / s;
    size_t base = (size_t)v * HH;
    h[base + lane]      = fmaxf(h[base + lane]      + a0 * inv + bias[lane],      0.f);
    h[base + lane + 32] = fmaxf(h[base + lane + 32] + a1 * inv + bias[lane + 32], 0.f);
    h[base + lane + 64] = fmaxf(h[base + lane + 64] + a2 * inv + bias[lane + 64], 0.f);
    h[base + lane + 96] = fmaxf(h[base + lane + 96] + a3 * inv + bias[lane + 96], 0.f);
}

// ---------------- edge head: out[e] = relu(P[s]+Q[d]) @ We2 + be2 ----------------
__global__ void edge_mlp(const float* __restrict__ P, const float* __restrict__ Q,
                         const int* __restrict__ src, const int* __restrict__ dst,
                         const float* __restrict__ We2, const float* __restrict__ be2,
                         float* __restrict__ out, int e) {
    int w = (blockIdx.x * blockDim.x + threadIdx.x) >> 5;
    int lane = threadIdx.x & 31;
    if (w >= e) return;
    int s = src[w], d = dst[w];
    const float* p = P + (size_t)s * HH;
    const float* q = Q + (size_t)d * HH;
    float o0 = 0.f, o1 = 0.f, o2 = 0.f;
#pragma unroll
    for (int i = 0; i < 4; i++) {
        int c = lane + 32 * i;
        float t = fmaxf(p[c] + q[c], 0.f);
        o0 += t * We2[c * 3 + 0];
        o1 += t * We2[c * 3 + 1];
        o2 += t * We2[c * 3 + 2];
    }
#pragma unroll
    for (int o = 16; o; o >>= 1) {
        o0 += __shfl_xor_sync(~0u, o0, o);
        o1 += __shfl_xor_sync(~0u, o1, o);
        o2 += __shfl_xor_sync(~0u, o2, o);
    }
    if (lane == 0) {
        size_t b = (size_t)w * 3;
        out[b + 0] = o0 + be2[0];
        out[b + 1] = o1 + be2[1];
        out[b + 2] = o2 + be2[2];
    }
}

// ---------------- graph mean ----------------
__global__ void zero128(float* o) { if (threadIdx.x < HH) o[threadIdx.x] = 0.f; }

__global__ void graph_mean(const float* __restrict__ h, float* __restrict__ out, int n) {
    int col = threadIdx.x;  // 128 threads
    float s = 0.f;
    for (int r = blockIdx.x; r < n; r += gridDim.x) s += h[(size_t)r * HH + col];
    atomicAdd(&out[col], s * (1.f / (float)n));
}

// ---------------- host launch ----------------
extern "C" void kernel_launch(void* const* d_in, const int* in_sizes, int n_in,
                              void* d_out, int out_size) {
    const float* x     = (const float*)d_in[0];
    const int*   ei    = (const int*)d_in[1];
    const float* W_emb = (const float*)d_in[2];
    const float* b_emb = (const float*)d_in[3];
    const float* gat_W = (const float*)d_in[4];
    const float* gat_as= (const float*)d_in[5];
    const float* gat_ad= (const float*)d_in[6];
    const float* gat_b = (const float*)d_in[7];
    const float* Wn1   = (const float*)d_in[8];
    const float* bn1   = (const float*)d_in[9];
    const float* Wn2   = (const float*)d_in[10];
    const float* bn2   = (const float*)d_in[11];
    const float* We1   = (const float*)d_in[12];
    const float* be1   = (const float*)d_in[13];
    const float* We2   = (const float*)d_in[14];
    const float* be2   = (const float*)d_in[15];
    float* out = (float*)d_out;

    const int n = in_sizes[0] / HH;   // 50000
    const int e = in_sizes[1] / 2;    // 800000
    const int* src = ei;
    const int* dst = ei + e;

    // resolve device scratch addresses
    float *h, *xw, *P, *Q, *as_, *ad_;
    int *cnt, *off, *csr;
    cudaGetSymbolAddress((void**)&h,   g_h);
    cudaGetSymbolAddress((void**)&xw,  g_xw);
    cudaGetSymbolAddress((void**)&P,   g_P);
    cudaGetSymbolAddress((void**)&Q,   g_Q);
    cudaGetSymbolAddress((void**)&as_, g_as);
    cudaGetSymbolAddress((void**)&ad_, g_ad);
    cudaGetSymbolAddress((void**)&cnt, g_cnt);
    cudaGetSymbolAddress((void**)&off, g_off);
    cudaGetSymbolAddress((void**)&csr, g_csr);

    // ---- CSR build (by dst, self loops included) ----
    init_cnt<<<(n + 255) / 256, 256>>>(cnt, n);
    count_dst<<<(e + 255) / 256, 256>>>(dst, cnt, e);
    scan_kernel<<<1, 1024>>>(cnt, off, n);
    csr_fill<<<(e + n + 255) / 256, 256>>>(src, dst, cnt, csr, e, n);

    dim3 gemm_grid2(2, (n + 63) / 64);   // Nc=128
    dim3 gemm_grid1(1, (n + 63) / 64);   // Nc=64

    // ---- embed: h = relu(x @ W_emb + b_emb) ----
    gemm128<true><<<gemm_grid2, 256>>>(x, W_emb, b_emb, h, n, HH);

    // ---- 3 GAT layers ----
    int warp_blocks_n = (n * 32 + 255) / 256;
    for (int l = 0; l < 3; l++) {
        gemm128<false><<<gemm_grid2, 256>>>(h, gat_W + (size_t)l * HH * HH, nullptr, xw, n, HH);
        compute_alpha<<<warp_blocks_n, 256>>>(xw, gat_as + l * HH, gat_ad + l * HH, as_, ad_, n);
        gat_aggregate<<<warp_blocks_n, 256>>>(xw, off, csr, as_, ad_, gat_b + l * HH, h, n);
    }

    // ---- edge-MLP factorization: P = h@We1_top + be1, Q = h@We1_bot ----
    gemm128<false><<<gemm_grid2, 256>>>(h, We1, be1, P, n, HH);
    gemm128<false><<<gemm_grid2, 256>>>(h, We1 + (size_t)HH * HH, nullptr, Q, n, HH);

    // ---- node head: out[0 : n*64] ----
    gemm128<true><<<gemm_grid2, 256>>>(h, Wn1, bn1, xw, n, HH);       // mid (reuse xw)
    gemm128<false><<<gemm_grid1, 256>>>(xw, Wn2, bn2, out, n, DOUT);

    // ---- edge head: out[n*64 : n*64 + e*3] ----
    int warp_blocks_e = ((long long)e * 32 + 255) / 256;
    edge_mlp<<<warp_blocks_e, 256>>>(P, Q, src, dst, We2, be2, out + (size_t)n * DOUT, e);

    // ---- graph mean: last 128 floats ----
    float* gout = out + (size_t)n * DOUT + (size_t)e * 3;
    zero128<<<1, 128>>>(gout);
    graph_mean<<<512, 128>>>(h, gout, n);
}

// round 8
// speedup vs baseline: 1.7379x; 1.7379x over previous
#include <cuda_runtime.h>
#include <cuda_bf16.h>
#include <cstdint>
#include <math.h>

#define NN 50000
#define EE 800000
#define HH 128
#define DOUT 64

// ---------------- device scratch (no allocations allowed) ----------------
__device__ float g_h[(size_t)NN * HH];
__device__ float g_xw[(size_t)NN * HH];
__device__ float g_P[(size_t)NN * HH];
__device__ float g_Q[(size_t)NN * HH];
__device__ float g_as[NN];
__device__ float g_ad[NN];
__device__ int   g_cnt[NN];          // histogram, then reused as scatter cursor
__device__ int   g_off[NN + 1];      // CSR offsets (by dst)
__device__ int   g_csr[EE + NN];     // src ids per dst bucket (incl. self loops)

// ---------------- CSR build ----------------
__global__ void init_cnt(int* cnt, int n) {
    int i = blockIdx.x * blockDim.x + threadIdx.x;
    if (i < n) cnt[i] = 1;  // self loop
}

__global__ void count_dst(const int* __restrict__ dst, int* cnt, int e) {
    int i = blockIdx.x * blockDim.x + threadIdx.x;
    if (i < e) atomicAdd(&cnt[dst[i]], 1);
}

// single-block exclusive scan; also initializes cursor (reuses cnt array)
__global__ void scan_kernel(int* cnt, int* off, int n) {
    __shared__ int sh[1024];
    __shared__ int carry;
    if (threadIdx.x == 0) carry = 0;
    __syncthreads();
    for (int base = 0; base < n; base += 1024) {
        int i = base + threadIdx.x;
        int v = (i < n) ? cnt[i] : 0;
        sh[threadIdx.x] = v;
        __syncthreads();
        for (int d = 1; d < 1024; d <<= 1) {
            int t = (threadIdx.x >= d) ? sh[threadIdx.x - d] : 0;
            __syncthreads();
            sh[threadIdx.x] += t;
            __syncthreads();
        }
        int incl = sh[threadIdx.x];
        int excl = incl - v + carry;
        if (i < n) { off[i] = excl; cnt[i] = excl; }  // cnt becomes cursor
        __syncthreads();
        if (threadIdx.x == 1023) carry += sh[1023];
        __syncthreads();
    }
    if (threadIdx.x == 0) off[n] = carry;
}

__global__ void csr_fill(const int* __restrict__ src, const int* __restrict__ dst,
                         int* cursor, int* csr, int e, int n) {
    int i = blockIdx.x * blockDim.x + threadIdx.x;
    int total = e + n;
    if (i >= total) return;
    int s, d;
    if (i < e) { s = src[i]; d = dst[i]; }
    else       { s = d = i - e; }
    int pos = atomicAdd(&cursor[d], 1);
    csr[pos] = s;
}

// ---------------- tf32 tensor-core GEMM ----------------
// C[M x Nc] = act(A[M x 128] @ B[128 x Nc] + bias)
// BM=128, BN=64, BK=16, 256 threads (8 warps in 4x2), warp tile 32x32,
// mma.sync.m16n8k8 tf32, fp32 accumulate.
__device__ __forceinline__ uint32_t f2tf32(float f) {
    uint32_t r;
    asm("cvt.rna.tf32.f32 %0, %1;" : "=r"(r) : "f"(f));
    return r;
}

template<bool RELU>
__global__ __launch_bounds__(256) void gemm_tf32(
        const float* __restrict__ A, const float* __restrict__ B,
        const float* __restrict__ bias, float* __restrict__ C,
        int M, int Nc) {
    __shared__ uint32_t As[128][20];   // BK=16 + 4 pad -> conflict-free frag loads
    __shared__ uint32_t Bs[16][72];    // BN=64 + 8 pad -> conflict-free frag loads

    const int tid  = threadIdx.x;
    const int warp = tid >> 5, lane = tid & 31;
    const int g  = lane >> 2;          // groupID 0..7
    const int tg = lane & 3;           // thread-in-group 0..3
    const int wm = warp & 3;           // warp row  (4)
    const int wn = warp >> 2;          // warp col  (2)
    const int row0 = blockIdx.y * 128;
    const int col0 = blockIdx.x * 64;

    float acc[2][4][4] = {};           // [mtile][ntile][c0..c3]

    for (int kt = 0; kt < 128; kt += 16) {
        // ---- stage A tile (128x16), convert to tf32 ----
#pragma unroll
        for (int j = 0; j < 2; j++) {
            int i  = tid + 256 * j;        // 0..511
            int r  = i >> 2;
            int c4 = (i & 3) << 2;
            int gr = row0 + r;
            float4 v = make_float4(0.f, 0.f, 0.f, 0.f);
            if (gr < M)
                v = *reinterpret_cast<const float4*>(A + (size_t)gr * 128 + kt + c4);
            uint4 t;
            t.x = f2tf32(v.x); t.y = f2tf32(v.y);
            t.z = f2tf32(v.z); t.w = f2tf32(v.w);
            *reinterpret_cast<uint4*>(&As[r][c4]) = t;
        }
        // ---- stage B tile (16x64), convert to tf32 ----
        {
            int r  = tid >> 4;
            int c4 = (tid & 15) << 2;
            float4 v = *reinterpret_cast<const float4*>(
                B + (size_t)(kt + r) * Nc + col0 + c4);
            uint4 t;
            t.x = f2tf32(v.x); t.y = f2tf32(v.y);
            t.z = f2tf32(v.z); t.w = f2tf32(v.w);
            *reinterpret_cast<uint4*>(&Bs[r][c4]) = t;
        }
        __syncthreads();

#pragma unroll
        for (int ks = 0; ks < 16; ks += 8) {
            uint32_t a[2][4], b[4][2];
#pragma unroll
            for (int mt = 0; mt < 2; mt++) {
                int r = wm * 32 + mt * 16 + g;
                a[mt][0] = As[r][ks + tg];
                a[mt][1] = As[r + 8][ks + tg];
                a[mt][2] = As[r][ks + tg + 4];
                a[mt][3] = As[r + 8][ks + tg + 4];
            }
#pragma unroll
            for (int nt = 0; nt < 4; nt++) {
                int nn = wn * 32 + nt * 8 + g;
                b[nt][0] = Bs[ks + tg][nn];
                b[nt][1] = Bs[ks + tg + 4][nn];
            }
#pragma unroll
            for (int mt = 0; mt < 2; mt++)
#pragma unroll
                for (int nt = 0; nt < 4; nt++) {
                    asm volatile(
                        "mma.sync.aligned.m16n8k8.row.col.f32.tf32.tf32.f32 "
                        "{%0,%1,%2,%3}, {%4,%5,%6,%7}, {%8,%9}, {%0,%1,%2,%3};\n"
                        : "+f"(acc[mt][nt][0]), "+f"(acc[mt][nt][1]),
                          "+f"(acc[mt][nt][2]), "+f"(acc[mt][nt][3])
                        : "r"(a[mt][0]), "r"(a[mt][1]), "r"(a[mt][2]), "r"(a[mt][3]),
                          "r"(b[nt][0]), "r"(b[nt][1]));
                }
        }
        __syncthreads();
    }

    // ---- epilogue ----
#pragma unroll
    for (int mt = 0; mt < 2; mt++) {
#pragma unroll
        for (int half = 0; half < 2; half++) {
            int gr = row0 + wm * 32 + mt * 16 + g + half * 8;
            if (gr >= M) continue;
#pragma unroll
            for (int nt = 0; nt < 4; nt++) {
                int gc = col0 + wn * 32 + nt * 8 + 2 * tg;
                float v0 = acc[mt][nt][half * 2 + 0];
                float v1 = acc[mt][nt][half * 2 + 1];
                if (bias) { v0 += bias[gc]; v1 += bias[gc + 1]; }
                if (RELU) { v0 = fmaxf(v0, 0.f); v1 = fmaxf(v1, 0.f); }
                *reinterpret_cast<float2*>(C + (size_t)gr * Nc + gc) =
                    make_float2(v0, v1);
            }
        }
    }
}

// ---------------- alpha_s / alpha_d: per-node dot products ----------------
__global__ void compute_alpha(const float* __restrict__ xw,
                              const float* __restrict__ a_s, const float* __restrict__ a_d,
                              float* __restrict__ out_s, float* __restrict__ out_d, int n) {
    int w = (blockIdx.x * blockDim.x + threadIdx.x) >> 5;
    int lane = threadIdx.x & 31;
    if (w >= n) return;
    const float* row = xw + (size_t)w * HH;
    float ss = 0.f, sd = 0.f;
#pragma unroll
    for (int i = 0; i < 4; i++) {
        int c = lane + 32 * i;
        float v = row[c];
        ss += v * a_s[c];
        sd += v * a_d[c];
    }
#pragma unroll
    for (int o = 16; o; o >>= 1) {
        ss += __shfl_xor_sync(~0u, ss, o);
        sd += __shfl_xor_sync(~0u, sd, o);
    }
    if (lane == 0) { out_s[w] = ss; out_d[w] = sd; }
}

// ---------------- GAT softmax + aggregation (warp per dst node, in-place h) --------------
__global__ void gat_aggregate(const float* __restrict__ xw,
                              const int* __restrict__ off, const int* __restrict__ csr,
                              const float* __restrict__ as_, const float* __restrict__ ad_,
                              const float* __restrict__ bias,
                              float* __restrict__ h, int n) {
    int v = (blockIdx.x * blockDim.x + threadIdx.x) >> 5;
    int lane = threadIdx.x & 31;
    if (v >= n) return;
    int o0 = off[v], o1 = off[v + 1];
    float ad = ad_[v];

    // pass 1: max logit (lanes parallel over edges)
    float m = -INFINITY;
    for (int e = o0 + lane; e < o1; e += 32) {
        int u = csr[e];
        float t = as_[u] + ad;
        t = (t > 0.f) ? t : 0.2f * t;
        m = fmaxf(m, t);
    }
#pragma unroll
    for (int o = 16; o; o >>= 1) m = fmaxf(m, __shfl_xor_sync(~0u, m, o));

    // pass 2: exp-weighted accumulate (warp marches edges together, 4 cols per lane)
    float s = 0.f;
    float a0 = 0.f, a1 = 0.f, a2 = 0.f, a3 = 0.f;
    for (int e = o0; e < o1; e++) {
        int u = csr[e];
        float t = as_[u] + ad;
        t = (t > 0.f) ? t : 0.2f * t;
        float p = __expf(t - m);
        s += p;
        const float* row = xw + (size_t)u * HH;
        a0 += p * row[lane];
        a1 += p * row[lane + 32];
        a2 += p * row[lane + 64];
        a3 += p * row[lane + 96];
    }
    float inv = 1.f / s;
    size_t base = (size_t)v * HH;
    h[base + lane]      = fmaxf(h[base + lane]      + a0 * inv + bias[lane],      0.f);
    h[base + lane + 32] = fmaxf(h[base + lane + 32] + a1 * inv + bias[lane + 32], 0.f);
    h[base + lane + 64] = fmaxf(h[base + lane + 64] + a2 * inv + bias[lane + 64], 0.f);
    h[base + lane + 96] = fmaxf(h[base + lane + 96] + a3 * inv + bias[lane + 96], 0.f);
}

// ---------------- edge head: out[e] = relu(P[s]+Q[d]) @ We2 + be2 ----------------
__global__ void edge_mlp(const float* __restrict__ P, const float* __restrict__ Q,
                         const int* __restrict__ src, const int* __restrict__ dst,
                         const float* __restrict__ We2, const float* __restrict__ be2,
                         float* __restrict__ out, int e) {
    int w = (blockIdx.x * blockDim.x + threadIdx.x) >> 5;
    int lane = threadIdx.x & 31;
    if (w >= e) return;
    int s = src[w], d = dst[w];
    const float* p = P + (size_t)s * HH;
    const float* q = Q + (size_t)d * HH;
    float o0 = 0.f, o1 = 0.f, o2 = 0.f;
#pragma unroll
    for (int i = 0; i < 4; i++) {
        int c = lane + 32 * i;
        float t = fmaxf(p[c] + q[c], 0.f);
        o0 += t * We2[c * 3 + 0];
        o1 += t * We2[c * 3 + 1];
        o2 += t * We2[c * 3 + 2];
    }
#pragma unroll
    for (int o = 16; o; o >>= 1) {
        o0 += __shfl_xor_sync(~0u, o0, o);
        o1 += __shfl_xor_sync(~0u, o1, o);
        o2 += __shfl_xor_sync(~0u, o2, o);
    }
    if (lane == 0) {
        size_t b = (size_t)w * 3;
        out[b + 0] = o0 + be2[0];
        out[b + 1] = o1 + be2[1];
        out[b + 2] = o2 + be2[2];
    }
}

// ---------------- graph mean ----------------
__global__ void zero128(float* o) { if (threadIdx.x < HH) o[threadIdx.x] = 0.f; }

__global__ void graph_mean(const float* __restrict__ h, float* __restrict__ out, int n) {
    int col = threadIdx.x;  // 128 threads
    float s = 0.f;
    for (int r = blockIdx.x; r < n; r += gridDim.x) s += h[(size_t)r * HH + col];
    atomicAdd(&out[col], s * (1.f / (float)n));
}

// ---------------- host launch ----------------
extern "C" void kernel_launch(void* const* d_in, const int* in_sizes, int n_in,
                              void* d_out, int out_size) {
    const float* x     = (const float*)d_in[0];
    const int*   ei    = (const int*)d_in[1];
    const float* W_emb = (const float*)d_in[2];
    const float* b_emb = (const float*)d_in[3];
    const float* gat_W = (const float*)d_in[4];
    const float* gat_as= (const float*)d_in[5];
    const float* gat_ad= (const float*)d_in[6];
    const float* gat_b = (const float*)d_in[7];
    const float* Wn1   = (const float*)d_in[8];
    const float* bn1   = (const float*)d_in[9];
    const float* Wn2   = (const float*)d_in[10];
    const float* bn2   = (const float*)d_in[11];
    const float* We1   = (const float*)d_in[12];
    const float* be1   = (const float*)d_in[13];
    const float* We2   = (const float*)d_in[14];
    const float* be2   = (const float*)d_in[15];
    float* out = (float*)d_out;

    const int n = in_sizes[0] / HH;   // 50000
    const int e = in_sizes[1] / 2;    // 800000
    const int* src = ei;
    const int* dst = ei + e;

    // resolve device scratch addresses
    float *h, *xw, *P, *Q, *as_, *ad_;
    int *cnt, *off, *csr;
    cudaGetSymbolAddress((void**)&h,   g_h);
    cudaGetSymbolAddress((void**)&xw,  g_xw);
    cudaGetSymbolAddress((void**)&P,   g_P);
    cudaGetSymbolAddress((void**)&Q,   g_Q);
    cudaGetSymbolAddress((void**)&as_, g_as);
    cudaGetSymbolAddress((void**)&ad_, g_ad);
    cudaGetSymbolAddress((void**)&cnt, g_cnt);
    cudaGetSymbolAddress((void**)&off, g_off);
    cudaGetSymbolAddress((void**)&csr, g_csr);

    // ---- CSR build (by dst, self loops included) ----
    init_cnt<<<(n + 255) / 256, 256>>>(cnt, n);
    count_dst<<<(e + 255) / 256, 256>>>(dst, cnt, e);
    scan_kernel<<<1, 1024>>>(cnt, off, n);
    csr_fill<<<(e + n + 255) / 256, 256>>>(src, dst, cnt, csr, e, n);

    dim3 tc_grid2(2, (n + 127) / 128);   // Nc=128
    dim3 tc_grid1(1, (n + 127) / 128);   // Nc=64

    // ---- embed: h = relu(x @ W_emb + b_emb) ----
    gemm_tf32<true><<<tc_grid2, 256>>>(x, W_emb, b_emb, h, n, HH);

    // ---- 3 GAT layers ----
    int warp_blocks_n = (n * 32 + 255) / 256;
    for (int l = 0; l < 3; l++) {
        gemm_tf32<false><<<tc_grid2, 256>>>(h, gat_W + (size_t)l * HH * HH, nullptr, xw, n, HH);
        compute_alpha<<<warp_blocks_n, 256>>>(xw, gat_as + l * HH, gat_ad + l * HH, as_, ad_, n);
        gat_aggregate<<<warp_blocks_n, 256>>>(xw, off, csr, as_, ad_, gat_b + l * HH, h, n);
    }

    // ---- edge-MLP factorization: P = h@We1_top + be1, Q = h@We1_bot ----
    gemm_tf32<false><<<tc_grid2, 256>>>(h, We1, be1, P, n, HH);
    gemm_tf32<false><<<tc_grid2, 256>>>(h, We1 + (size_t)HH * HH, nullptr, Q, n, HH);

    // ---- node head: out[0 : n*64] ----
    gemm_tf32<true><<<tc_grid2, 256>>>(h, Wn1, bn1, xw, n, HH);       // mid (reuse xw)
    gemm_tf32<false><<<tc_grid1, 256>>>(xw, Wn2, bn2, out, n, DOUT);

    // ---- edge head: out[n*64 : n*64 + e*3] ----
    int warp_blocks_e = ((long long)e * 32 + 255) / 256;
    edge_mlp<<<warp_blocks_e, 256>>>(P, Q, src, dst, We2, be2, out + (size_t)n * DOUT, e);

    // ---- graph mean: last 128 floats ----
    float* gout = out + (size_t)n * DOUT + (size_t)e * 3;
    zero128<<<1, 128>>>(gout);
    graph_mean<<<512, 128>>>(h, gout, n);
}

// round 9
// speedup vs baseline: 1.9325x; 1.1120x over previous
#include <cuda_runtime.h>
#include <cuda_bf16.h>
#include <cstdint>
#include <math.h>

#define NN 50000
#define EE 800000
#define HH 128
#define DOUT 64

// ---------------- device scratch (no allocations allowed) ----------------
__device__ float g_h[(size_t)NN * HH];
__device__ float g_xw[(size_t)NN * HH];
__device__ float g_P[(size_t)NN * HH];
__device__ float g_Q[(size_t)NN * HH];
__device__ float g_as[NN];
__device__ float g_ad[NN];
__device__ int   g_cnt[NN];          // histogram, then reused as scatter cursor
__device__ int   g_off[NN + 1];      // CSR offsets (by dst)
__device__ int   g_csr[EE + NN];     // src ids per dst bucket (incl. self loops)

// ---------------- CSR build ----------------
__global__ void init_cnt(int* cnt, int n) {
    int i = blockIdx.x * blockDim.x + threadIdx.x;
    if (i < n) cnt[i] = 1;  // self loop
}

__global__ void count_dst(const int* __restrict__ dst, int* cnt, int e) {
    int i = blockIdx.x * blockDim.x + threadIdx.x;
    if (i < e) atomicAdd(&cnt[dst[i]], 1);
}

// single-block exclusive scan via warp shuffles; also initializes cursor
__global__ void scan_kernel(int* cnt, int* off, int n) {
    __shared__ int wsum[32];
    __shared__ int carry_s;
    const int lane = threadIdx.x & 31, wid = threadIdx.x >> 5;
    if (threadIdx.x == 0) carry_s = 0;
    __syncthreads();
    for (int base = 0; base < n; base += 1024) {
        int i = base + threadIdx.x;
        int v = (i < n) ? cnt[i] : 0;
        int x = v;
#pragma unroll
        for (int d = 1; d < 32; d <<= 1) {
            int t = __shfl_up_sync(~0u, x, d);
            if (lane >= d) x += t;
        }
        if (lane == 31) wsum[wid] = x;
        __syncthreads();
        if (wid == 0) {
            int y = wsum[lane];
#pragma unroll
            for (int d = 1; d < 32; d <<= 1) {
                int t = __shfl_up_sync(~0u, y, d);
                if (lane >= d) y += t;
            }
            wsum[lane] = y;
        }
        __syncthreads();
        int incl = x + (wid ? wsum[wid - 1] : 0) + carry_s;
        int excl = incl - v;
        if (i < n) { off[i] = excl; cnt[i] = excl; }  // cnt becomes cursor
        __syncthreads();
        if (threadIdx.x == 0) carry_s += wsum[31];
        __syncthreads();
    }
    if (threadIdx.x == 0) off[n] = carry_s;
}

__global__ void csr_fill(const int* __restrict__ src, const int* __restrict__ dst,
                         int* cursor, int* csr, int e, int n) {
    int i = blockIdx.x * blockDim.x + threadIdx.x;
    int total = e + n;
    if (i >= total) return;
    int s, d;
    if (i < e) { s = src[i]; d = dst[i]; }
    else       { s = d = i - e; }
    int pos = atomicAdd(&cursor[d], 1);
    csr[pos] = s;
}

// ---------------- tf32 tensor-core GEMM, cp.async triple-buffered ----------------
// C[M x Nc] = act(A[M x 128] @ B[128 x Nc] + bias)
// BM=128, BN=64, BK=16, 256 threads (8 warps in 4x2), warp tile 32x32,
// mma.sync.m16n8k8 tf32, fp32 accumulate; fp32 staged via cp.async,
// cvt.rna to tf32 at fragment-load time.
__device__ __forceinline__ uint32_t f2tf32(float f) {
    uint32_t r;
    asm("cvt.rna.tf32.f32 %0, %1;" : "=r"(r) : "f"(f));
    return r;
}

__device__ __forceinline__ void cp16(void* dst, const void* src, bool p) {
    uint32_t d = (uint32_t)__cvta_generic_to_shared(dst);
    int sz = p ? 16 : 0;
    asm volatile("cp.async.ca.shared.global [%0], [%1], 16, %2;\n"
                 :: "r"(d), "l"(src), "r"(sz));
}

__device__ __forceinline__ void stage_tile(
        const float* __restrict__ A, const float* __restrict__ B,
        int M, int Nc, int row0, int col0, int kt,
        float (*As)[20], float (*Bs)[72], int tid) {
#pragma unroll
    for (int j = 0; j < 2; j++) {
        int i  = tid + 256 * j;          // 0..511 -> 128 rows x 4 chunks
        int r  = i >> 2;
        int c4 = (i & 3) << 2;
        int gr = row0 + r;
        bool ok = gr < M;
        const float* src = A + (size_t)(ok ? gr : 0) * 128 + kt + c4;
        cp16(&As[r][c4], src, ok);
    }
    {
        int r  = tid >> 4;               // 16 rows x 16 chunks
        int c4 = (tid & 15) << 2;
        const float* src = B + (size_t)(kt + r) * Nc + col0 + c4;
        cp16(&Bs[r][c4], src, true);
    }
    asm volatile("cp.async.commit_group;\n");
}

template<bool RELU>
__global__ __launch_bounds__(256) void gemm_tf32(
        const float* __restrict__ A, const float* __restrict__ B,
        const float* __restrict__ bias, float* __restrict__ C,
        int M, int Nc) {
    __shared__ __align__(16) float As[3][128][20];  // pad 4 -> conflict-free
    __shared__ __align__(16) float Bs[3][16][72];   // pad 8 -> conflict-free

    const int tid  = threadIdx.x;
    const int warp = tid >> 5, lane = tid & 31;
    const int g  = lane >> 2;          // groupID 0..7
    const int tg = lane & 3;           // thread-in-group 0..3
    const int wm = warp & 3;           // warp row  (4)
    const int wn = warp >> 2;          // warp col  (2)
    const int row0 = blockIdx.y * 128;
    const int col0 = blockIdx.x * 64;

    float acc[2][4][4] = {};           // [mtile][ntile][c0..c3]

    // prologue: tiles 0 and 1 in flight
    stage_tile(A, B, M, Nc, row0, col0, 0,  As[0], Bs[0], tid);
    stage_tile(A, B, M, Nc, row0, col0, 16, As[1], Bs[1], tid);

#pragma unroll
    for (int kt = 0; kt < 8; kt++) {
        if (kt < 7) asm volatile("cp.async.wait_group 1;\n");
        else        asm volatile("cp.async.wait_group 0;\n");
        __syncthreads();
        if (kt + 2 < 8)
            stage_tile(A, B, M, Nc, row0, col0, (kt + 2) * 16,
                       As[(kt + 2) % 3], Bs[(kt + 2) % 3], tid);

        const float (*Asb)[20] = As[kt % 3];
        const float (*Bsb)[72] = Bs[kt % 3];
#pragma unroll
        for (int ks = 0; ks < 16; ks += 8) {
            uint32_t a[2][4], b[4][2];
#pragma unroll
            for (int mt = 0; mt < 2; mt++) {
                int r = wm * 32 + mt * 16 + g;
                a[mt][0] = f2tf32(Asb[r][ks + tg]);
                a[mt][1] = f2tf32(Asb[r + 8][ks + tg]);
                a[mt][2] = f2tf32(Asb[r][ks + tg + 4]);
                a[mt][3] = f2tf32(Asb[r + 8][ks + tg + 4]);
            }
#pragma unroll
            for (int nt = 0; nt < 4; nt++) {
                int nn = wn * 32 + nt * 8 + g;
                b[nt][0] = f2tf32(Bsb[ks + tg][nn]);
                b[nt][1] = f2tf32(Bsb[ks + tg + 4][nn]);
            }
#pragma unroll
            for (int mt = 0; mt < 2; mt++)
#pragma unroll
                for (int nt = 0; nt < 4; nt++) {
                    asm volatile(
                        "mma.sync.aligned.m16n8k8.row.col.f32.tf32.tf32.f32 "
                        "{%0,%1,%2,%3}, {%4,%5,%6,%7}, {%8,%9}, {%0,%1,%2,%3};\n"
                        : "+f"(acc[mt][nt][0]), "+f"(acc[mt][nt][1]),
                          "+f"(acc[mt][nt][2]), "+f"(acc[mt][nt][3])
                        : "r"(a[mt][0]), "r"(a[mt][1]), "r"(a[mt][2]), "r"(a[mt][3]),
                          "r"(b[nt][0]), "r"(b[nt][1]));
                }
        }
    }

    // ---- epilogue ----
#pragma unroll
    for (int mt = 0; mt < 2; mt++) {
#pragma unroll
        for (int half = 0; half < 2; half++) {
            int gr = row0 + wm * 32 + mt * 16 + g + half * 8;
            if (gr >= M) continue;
#pragma unroll
            for (int nt = 0; nt < 4; nt++) {
                int gc = col0 + wn * 32 + nt * 8 + 2 * tg;
                float v0 = acc[mt][nt][half * 2 + 0];
                float v1 = acc[mt][nt][half * 2 + 1];
                if (bias) { v0 += bias[gc]; v1 += bias[gc + 1]; }
                if (RELU) { v0 = fmaxf(v0, 0.f); v1 = fmaxf(v1, 0.f); }
                *reinterpret_cast<float2*>(C + (size_t)gr * Nc + gc) =
                    make_float2(v0, v1);
            }
        }
    }
}

// ---------------- alpha_s / alpha_d: per-node dot products ----------------
__global__ void compute_alpha(const float* __restrict__ xw,
                              const float* __restrict__ a_s, const float* __restrict__ a_d,
                              float* __restrict__ out_s, float* __restrict__ out_d, int n) {
    int w = (blockIdx.x * blockDim.x + threadIdx.x) >> 5;
    int lane = threadIdx.x & 31;
    if (w >= n) return;
    const float* row = xw + (size_t)w * HH;
    float ss = 0.f, sd = 0.f;
#pragma unroll
    for (int i = 0; i < 4; i++) {
        int c = lane + 32 * i;
        float v = row[c];
        ss += v * a_s[c];
        sd += v * a_d[c];
    }
#pragma unroll
    for (int o = 16; o; o >>= 1) {
        ss += __shfl_xor_sync(~0u, ss, o);
        sd += __shfl_xor_sync(~0u, sd, o);
    }
    if (lane == 0) { out_s[w] = ss; out_d[w] = sd; }
}

// ---------------- GAT softmax + aggregation (warp per dst node, in-place h) --------------
__global__ void gat_aggregate(const float* __restrict__ xw,
                              const int* __restrict__ off, const int* __restrict__ csr,
                              const float* __restrict__ as_, const float* __restrict__ ad_,
                              const float* __restrict__ bias,
                              float* __restrict__ h, int n) {
    int v = (blockIdx.x * blockDim.x + threadIdx.x) >> 5;
    int lane = threadIdx.x & 31;
    if (v >= n) return;
    int o0 = off[v], o1 = off[v + 1];
    float ad = ad_[v];

    // pass 1: max logit (lanes parallel over edges)
    float m = -INFINITY;
    for (int e = o0 + lane; e < o1; e += 32) {
        int u = csr[e];
        float t = as_[u] + ad;
        t = (t > 0.f) ? t : 0.2f * t;
        m = fmaxf(m, t);
    }
#pragma unroll
    for (int o = 16; o; o >>= 1) m = fmaxf(m, __shfl_xor_sync(~0u, m, o));

    // pass 2: exp-weighted accumulate, unrolled x2 for MLP
    float s = 0.f;
    float a0 = 0.f, a1 = 0.f, a2 = 0.f, a3 = 0.f;
    float c0 = 0.f, c1 = 0.f, c2 = 0.f, c3 = 0.f;
    int e = o0;
    for (; e + 2 <= o1; e += 2) {
        int u0 = csr[e], u1 = csr[e + 1];
        float t0 = as_[u0] + ad; t0 = (t0 > 0.f) ? t0 : 0.2f * t0;
        float t1 = as_[u1] + ad; t1 = (t1 > 0.f) ? t1 : 0.2f * t1;
        float p0 = __expf(t0 - m);
        float p1 = __expf(t1 - m);
        s += p0 + p1;
        const float* r0 = xw + (size_t)u0 * HH;
        const float* r1 = xw + (size_t)u1 * HH;
        a0 += p0 * r0[lane];      c0 += p1 * r1[lane];
        a1 += p0 * r0[lane + 32]; c1 += p1 * r1[lane + 32];
        a2 += p0 * r0[lane + 64]; c2 += p1 * r1[lane + 64];
        a3 += p0 * r0[lane + 96]; c3 += p1 * r1[lane + 96];
    }
    if (e < o1) {
        int u = csr[e];
        float t = as_[u] + ad; t = (t > 0.f) ? t : 0.2f * t;
        float p = __expf(t - m);
        s += p;
        const float* row = xw + (size_t)u * HH;
        a0 += p * row[lane];
        a1 += p * row[lane + 32];
        a2 += p * row[lane + 64];
        a3 += p * row[lane + 96];
    }
    a0 += c0; a1 += c1; a2 += c2; a3 += c3;

    float inv = 1.f / s;
    size_t base = (size_t)v * HH;
    h[base + lane]      = fmaxf(h[base + lane]      + a0 * inv + bias[lane],      0.f);
    h[base + lane + 32] = fmaxf(h[base + lane + 32] + a1 * inv + bias[lane + 32], 0.f);
    h[base + lane + 64] = fmaxf(h[base + lane + 64] + a2 * inv + bias[lane + 64], 0.f);
    h[base + lane + 96] = fmaxf(h[base + lane + 96] + a3 * inv + bias[lane + 96], 0.f);
}

// ---------------- edge head: out[e] = relu(P[s]+Q[d]) @ We2 + be2 ----------------
__global__ void edge_mlp(const float* __restrict__ P, const float* __restrict__ Q,
                         const int* __restrict__ src, const int* __restrict__ dst,
                         const float* __restrict__ We2, const float* __restrict__ be2,
                         float* __restrict__ out, int e) {
    int w = (blockIdx.x * blockDim.x + threadIdx.x) >> 5;
    int lane = threadIdx.x & 31;
    if (w >= e) return;
    int s = src[w], d = dst[w];
    const float* p = P + (size_t)s * HH;
    const float* q = Q + (size_t)d * HH;
    float o0 = 0.f, o1 = 0.f, o2 = 0.f;
#pragma unroll
    for (int i = 0; i < 4; i++) {
        int c = lane + 32 * i;
        float t = fmaxf(p[c] + q[c], 0.f);
        o0 += t * We2[c * 3 + 0];
        o1 += t * We2[c * 3 + 1];
        o2 += t * We2[c * 3 + 2];
    }
#pragma unroll
    for (int o = 16; o; o >>= 1) {
        o0 += __shfl_xor_sync(~0u, o0, o);
        o1 += __shfl_xor_sync(~0u, o1, o);
        o2 += __shfl_xor_sync(~0u, o2, o);
    }
    if (lane == 0) {
        size_t b = (size_t)w * 3;
        out[b + 0] = o0 + be2[0];
        out[b + 1] = o1 + be2[1];
        out[b + 2] = o2 + be2[2];
    }
}

// ---------------- graph mean ----------------
__global__ void zero128(float* o) { if (threadIdx.x < HH) o[threadIdx.x] = 0.f; }

__global__ void graph_mean(const float* __restrict__ h, float* __restrict__ out, int n) {
    int col = threadIdx.x;  // 128 threads
    float s = 0.f;
    for (int r = blockIdx.x; r < n; r += gridDim.x) s += h[(size_t)r * HH + col];
    atomicAdd(&out[col], s * (1.f / (float)n));
}

// ---------------- host launch ----------------
extern "C" void kernel_launch(void* const* d_in, const int* in_sizes, int n_in,
                              void* d_out, int out_size) {
    const float* x     = (const float*)d_in[0];
    const int*   ei    = (const int*)d_in[1];
    const float* W_emb = (const float*)d_in[2];
    const float* b_emb = (const float*)d_in[3];
    const float* gat_W = (const float*)d_in[4];
    const float* gat_as= (const float*)d_in[5];
    const float* gat_ad= (const float*)d_in[6];
    const float* gat_b = (const float*)d_in[7];
    const float* Wn1   = (const float*)d_in[8];
    const float* bn1   = (const float*)d_in[9];
    const float* Wn2   = (const float*)d_in[10];
    const float* bn2   = (const float*)d_in[11];
    const float* We1   = (const float*)d_in[12];
    const float* be1   = (const float*)d_in[13];
    const float* We2   = (const float*)d_in[14];
    const float* be2   = (const float*)d_in[15];
    float* out = (float*)d_out;

    const int n = in_sizes[0] / HH;   // 50000
    const int e = in_sizes[1] / 2;    // 800000
    const int* src = ei;
    const int* dst = ei + e;

    // resolve device scratch addresses
    float *h, *xw, *P, *Q, *as_, *ad_;
    int *cnt, *off, *csr;
    cudaGetSymbolAddress((void**)&h,   g_h);
    cudaGetSymbolAddress((void**)&xw,  g_xw);
    cudaGetSymbolAddress((void**)&P,   g_P);
    cudaGetSymbolAddress((void**)&Q,   g_Q);
    cudaGetSymbolAddress((void**)&as_, g_as);
    cudaGetSymbolAddress((void**)&ad_, g_ad);
    cudaGetSymbolAddress((void**)&cnt, g_cnt);
    cudaGetSymbolAddress((void**)&off, g_off);
    cudaGetSymbolAddress((void**)&csr, g_csr);

    // ---- CSR build (by dst, self loops included) ----
    init_cnt<<<(n + 255) / 256, 256>>>(cnt, n);
    count_dst<<<(e + 255) / 256, 256>>>(dst, cnt, e);
    scan_kernel<<<1, 1024>>>(cnt, off, n);
    csr_fill<<<(e + n + 255) / 256, 256>>>(src, dst, cnt, csr, e, n);

    dim3 tc_grid2(2, (n + 127) / 128);   // Nc=128
    dim3 tc_grid1(1, (n + 127) / 128);   // Nc=64

    // ---- embed: h = relu(x @ W_emb + b_emb) ----
    gemm_tf32<true><<<tc_grid2, 256>>>(x, W_emb, b_emb, h, n, HH);

    // ---- 3 GAT layers ----
    int warp_blocks_n = (n * 32 + 255) / 256;
    for (int l = 0; l < 3; l++) {
        gemm_tf32<false><<<tc_grid2, 256>>>(h, gat_W + (size_t)l * HH * HH, nullptr, xw, n, HH);
        compute_alpha<<<warp_blocks_n, 256>>>(xw, gat_as + l * HH, gat_ad + l * HH, as_, ad_, n);
        gat_aggregate<<<warp_blocks_n, 256>>>(xw, off, csr, as_, ad_, gat_b + l * HH, h, n);
    }

    // ---- edge-MLP factorization: P = h@We1_top + be1, Q = h@We1_bot ----
    gemm_tf32<false><<<tc_grid2, 256>>>(h, We1, be1, P, n, HH);
    gemm_tf32<false><<<tc_grid2, 256>>>(h, We1 + (size_t)HH * HH, nullptr, Q, n, HH);

    // ---- node head: out[0 : n*64] ----
    gemm_tf32<true><<<tc_grid2, 256>>>(h, Wn1, bn1, xw, n, HH);       // mid (reuse xw)
    gemm_tf32<false><<<tc_grid1, 256>>>(xw, Wn2, bn2, out, n, DOUT);

    // ---- edge head: out[n*64 : n*64 + e*3] ----
    int warp_blocks_e = ((long long)e * 32 + 255) / 256;
    edge_mlp<<<warp_blocks_e, 256>>>(P, Q, src, dst, We2, be2, out + (size_t)n * DOUT, e);

    // ---- graph mean: last 128 floats ----
    float* gout = out + (size_t)n * DOUT + (size_t)e * 3;
    zero128<<<1, 128>>>(gout);
    graph_mean<<<512, 128>>>(h, gout, n);
}